// round 11
// baseline (speedup 1.0000x reference)
#include <cuda_runtime.h>
#include <cstdint>

#define NPTS   8192
#define NFEAT  256
#define SPLITS 64
#define CHUNK  (NPTS / SPLITS)      // 128 refs = 64 pairs -> 2KB smem
#define QTILES 16                   // 512 queries per block, 4 per thread
#define NN_BLOCKS   (QTILES * SPLITS)       // 1024 -> single wave
#define COPY_BLOCKS 128

// Per-split packed argmin partials: (ordered_d2_bits << 32) | ref_index.
__device__ unsigned long long g_part[SPLITS * NPTS];
__device__ int g_inds[NPTS];

__device__ __forceinline__ unsigned int float_order(float f) {
    unsigned int u = __float_as_uint(f);
    return (u & 0x80000000u) ? ~u : (u | 0x80000000u);
}

// ---- packed f32x2 helpers (FFMA2 is PTX-only; ptxas won't auto-fuse) ----
__device__ __forceinline__ uint64_t bcast2(float f) {
    uint64_t r; asm("mov.b64 %0, {%1, %1};" : "=l"(r) : "f"(f)); return r;
}
__device__ __forceinline__ uint64_t fma2(uint64_t a, uint64_t b, uint64_t c) {
    uint64_t d; asm("fma.rn.f32x2 %0, %1, %2, %3;" : "=l"(d) : "l"(a), "l"(b), "l"(c));
    return d;
}
__device__ __forceinline__ void unpack2(uint64_t v, float& lo, float& hi) {
    asm("mov.b64 {%0, %1}, %2;" : "=f"(lo), "=f"(hi) : "l"(v));
}
__device__ __forceinline__ void lds_v2u64(uint32_t addr, uint64_t& a, uint64_t& b) {
    asm volatile("ld.shared.v2.u64 {%0, %1}, [%2];" : "=l"(a), "=l"(b) : "r"(addr));
}

// grid(NN_BLOCKS + COPY_BLOCKS), block(128). No occupancy cap (round 9:
// forcing min-blocks spilled the hot loop).
// Blocks [0, NN_BLOCKS): argmin. qtile = b & 15, split = b >> 4.
//   Each thread owns 4 queries: q0 + {0,128,256,384}.
// Blocks [NN_BLOCKS, +COPY_BLOCKS): stream-copy emb2 -> out upper half.
__global__ void __launch_bounds__(128) nn_argmin_kernel(
    const float* __restrict__ t1,   // refs  [3, NPTS]
    const float* __restrict__ t2,   // query [3, NPTS]
    const float* __restrict__ emb2,
    float* __restrict__ out)
{
    const int tid = threadIdx.x;

    if (blockIdx.x >= NN_BLOCKS) {
        const int c = blockIdx.x - NN_BLOCKS;
        const float4* src = (const float4*)emb2;
        float4* dst = (float4*)(out + (size_t)NFEAT * NPTS);
        #pragma unroll
        for (int i = 0; i < 32; ++i) {
            const int o = c * 4096 + i * 128 + tid;
            dst[o] = src[o];
        }
        return;
    }

    __shared__ float4 refs[CHUNK];          // 128 float4 = 2KB
    const int split = blockIdx.x >> 4;
    const int qtile = blockIdx.x & 15;
    const int base  = split * CHUNK;

    // Prologue: threads 0..63 each pack one ref pair:
    // pair i -> {x0,x1,y0,y1},{z0,z1,w0,w1}.
    if (tid < CHUNK / 2) {
        const int r2 = tid * 2;
        float2 x2 = *(const float2*)(t1 + base + r2);
        float2 y2 = *(const float2*)(t1 + NPTS + base + r2);
        float2 z2 = *(const float2*)(t1 + 2 * NPTS + base + r2);
        float w0 = fmaf(x2.x, x2.x, fmaf(y2.x, y2.x, z2.x * z2.x));
        float w1 = fmaf(x2.y, x2.y, fmaf(y2.y, y2.y, z2.y * z2.y));
        refs[2 * tid]     = make_float4(x2.x, x2.y, y2.x, y2.y);
        refs[2 * tid + 1] = make_float4(z2.x, z2.y, w0, w1);
    }
    __syncthreads();

    const int q0 = qtile * 512 + tid;
    uint64_t aa[4], bb[4], cc[4];
    #pragma unroll
    for (int k = 0; k < 4; ++k) {
        const int q = q0 + k * 128;
        aa[k] = bcast2(-2.0f * t2[q]);
        bb[k] = bcast2(-2.0f * t2[NPTS + q]);
        cc[k] = bcast2(-2.0f * t2[2 * NPTS + q]);
    }

    // One running min + winning-pair index per query; parity deferred.
    float gm[4] = {3.4e38f, 3.4e38f, 3.4e38f, 3.4e38f};
    int   bi[4] = {0, 0, 0, 0};

    const uint32_t sbase = (uint32_t)__cvta_generic_to_shared(refs);

    // v = fma(a,x, fma(b,y, fma(c,z, w))) — identical chain to all passing
    // kernels: every argmin decision is bit-identical. Strict '<' on
    // m = min(ve,vo): bi records the FIRST pair attaining the final min.
    #pragma unroll 2
    for (int i = 0; i < CHUNK / 2; ++i) {
        uint64_t x01, y01, z01, w01;
        lds_v2u64(sbase + i * 32,      x01, y01);
        lds_v2u64(sbase + i * 32 + 16, z01, w01);

        #pragma unroll
        for (int k = 0; k < 4; ++k) {
            uint64_t vp = fma2(aa[k], x01, fma2(bb[k], y01, fma2(cc[k], z01, w01)));
            float ve, vo;
            unpack2(vp, ve, vo);
            float m = fminf(ve, vo);
            bool p = m < gm[k];
            gm[k] = fminf(gm[k], m);
            bi[k] = p ? i : bi[k];
        }
    }

    // Epilogue: resolve parity by recomputing the winning pair (bit-exact;
    // gm is a bit-copy of one half). ve == gm -> even (lower index) wins,
    // preserving first-occurrence on intra-pair ties.
    #pragma unroll
    for (int k = 0; k < 4; ++k) {
        uint64_t x01, y01, z01, w01;
        lds_v2u64(sbase + bi[k] * 32,      x01, y01);
        lds_v2u64(sbase + bi[k] * 32 + 16, z01, w01);
        uint64_t vp = fma2(aa[k], x01, fma2(bb[k], y01, fma2(cc[k], z01, w01)));
        float ve, vo; unpack2(vp, ve, vo);
        const int idx = base + 2 * bi[k] + ((ve == gm[k]) ? 0 : 1);
        g_part[split * NPTS + q0 + k * 128] =
            ((unsigned long long)float_order(gm[k]) << 32) | (unsigned int)idx;
    }
}

// grid(NPTS/256), block(256): min-combine SPLITS partials -> g_inds.
__global__ void __launch_bounds__(256) combine_kernel() {
    const int q = blockIdx.x * 256 + threadIdx.x;
    unsigned long long m = g_part[q];
    #pragma unroll
    for (int s = 1; s < SPLITS; ++s) {
        unsigned long long v = g_part[s * NPTS + q];
        m = (v < m) ? v : m;
    }
    g_inds[q] = (int)(unsigned int)(m & 0xFFFFFFFFull);
}

// grid(2*NFEAT), block(256). Two blocks per emb1 row: each loads the full
// row into smem (twin hits L2) and gathers half the queries. LDS gather
// avoids L1tex wavefront amplification; stores are float4 coalesced.
__global__ void __launch_bounds__(256) gather_kernel(
    const float* __restrict__ emb1,
    float* __restrict__ out)
{
    const int tid  = threadIdx.x;
    const int row  = blockIdx.x >> 1;
    const int half = blockIdx.x & 1;

    __shared__ float srow[NPTS];
    const float4* rowsrc = (const float4*)(emb1 + (size_t)row * NPTS);
    float4* srow4 = (float4*)srow;
    #pragma unroll
    for (int i = 0; i < NPTS / 4 / 256; ++i)
        srow4[i * 256 + tid] = rowsrc[i * 256 + tid];
    __syncthreads();

    const int jhalf = half * (NPTS / 2);
    float* dst = out + (size_t)row * NPTS + jhalf;
    const int* inds = g_inds + jhalf;
    #pragma unroll
    for (int k = 0; k < 4; ++k) {
        const int j = tid * 4 + k * 1024;
        int4 iv = *(const int4*)(inds + j);
        float4 v = make_float4(srow[iv.x], srow[iv.y], srow[iv.z], srow[iv.w]);
        *(float4*)(dst + j) = v;
    }
}

extern "C" void kernel_launch(void* const* d_in, const int* in_sizes, int n_in,
                              void* d_out, int out_size) {
    const float* emb1 = (const float*)d_in[0];
    const float* emb2 = (const float*)d_in[1];
    const float* t1   = (const float*)d_in[2];
    const float* t2   = (const float*)d_in[3];
    float* out = (float*)d_out;

    nn_argmin_kernel<<<NN_BLOCKS + COPY_BLOCKS, 128>>>(t1, t2, emb2, out);
    combine_kernel<<<NPTS / 256, 256>>>();
    gather_kernel<<<2 * NFEAT, 256>>>(emb1, out);
}

// round 12
// speedup vs baseline: 1.0736x; 1.0736x over previous
#include <cuda_runtime.h>
#include <cstdint>

#define NPTS   8192
#define NFEAT  256
#define SPLITS 64
#define CHUNK  (NPTS / SPLITS)      // 128 refs = 64 pairs -> 2KB smem
#define NN_BLOCKS   (NPTS / 256 * SPLITS)   // 2048
#define COPY_BLOCKS 128

// Per-split packed argmin partials: (ordered_d2_bits << 32) | ref_index.
__device__ unsigned long long g_part[SPLITS * NPTS];
__device__ int g_inds[NPTS];

__device__ __forceinline__ unsigned int float_order(float f) {
    unsigned int u = __float_as_uint(f);
    return (u & 0x80000000u) ? ~u : (u | 0x80000000u);
}

// ---- packed f32x2 helpers (FFMA2 is PTX-only; ptxas won't auto-fuse) ----
__device__ __forceinline__ uint64_t bcast2(float f) {
    uint64_t r; asm("mov.b64 %0, {%1, %1};" : "=l"(r) : "f"(f)); return r;
}
__device__ __forceinline__ uint64_t fma2(uint64_t a, uint64_t b, uint64_t c) {
    uint64_t d; asm("fma.rn.f32x2 %0, %1, %2, %3;" : "=l"(d) : "l"(a), "l"(b), "l"(c));
    return d;
}
__device__ __forceinline__ void unpack2(uint64_t v, float& lo, float& hi) {
    asm("mov.b64 {%0, %1}, %2;" : "=f"(lo), "=f"(hi) : "l"(v));
}
__device__ __forceinline__ void lds_v2u64(uint32_t addr, uint64_t& a, uint64_t& b) {
    asm volatile("ld.shared.v2.u64 {%0, %1}, [%2];" : "=l"(a), "=l"(b) : "r"(addr));
}

// ===== nn kernel: EXACT round-10 structure (best measured: 16.9us) =====
// grid(NN_BLOCKS + COPY_BLOCKS), block(128). No occupancy cap (caps spill).
// Blocks [0, NN_BLOCKS): argmin. qtile = b & 31, split = b >> 5.
// Blocks [NN_BLOCKS, +COPY_BLOCKS): stream-copy emb2 -> out upper half.
__global__ void __launch_bounds__(128) nn_argmin_kernel(
    const float* __restrict__ t1,   // refs  [3, NPTS]
    const float* __restrict__ t2,   // query [3, NPTS]
    const float* __restrict__ emb2,
    float* __restrict__ out)
{
    const int tid = threadIdx.x;

    if (blockIdx.x >= NN_BLOCKS) {
        const int c = blockIdx.x - NN_BLOCKS;
        const float4* src = (const float4*)emb2;
        float4* dst = (float4*)(out + (size_t)NFEAT * NPTS);
        #pragma unroll
        for (int i = 0; i < 32; ++i) {
            const int o = c * 4096 + i * 128 + tid;
            dst[o] = src[o];
        }
        return;
    }

    __shared__ float4 refs[CHUNK];          // 128 float4 = 2KB
    const int split = blockIdx.x >> 5;
    const int qtile = blockIdx.x & 31;
    const int base  = split * CHUNK;

    // Prologue: threads 0..63 each pack one ref pair:
    // pair i -> {x0,x1,y0,y1},{z0,z1,w0,w1}.
    if (tid < CHUNK / 2) {
        const int r2 = tid * 2;
        float2 x2 = *(const float2*)(t1 + base + r2);
        float2 y2 = *(const float2*)(t1 + NPTS + base + r2);
        float2 z2 = *(const float2*)(t1 + 2 * NPTS + base + r2);
        float w0 = fmaf(x2.x, x2.x, fmaf(y2.x, y2.x, z2.x * z2.x));
        float w1 = fmaf(x2.y, x2.y, fmaf(y2.y, y2.y, z2.y * z2.y));
        refs[2 * tid]     = make_float4(x2.x, x2.y, y2.x, y2.y);
        refs[2 * tid + 1] = make_float4(z2.x, z2.y, w0, w1);
    }
    __syncthreads();

    const int q0 = qtile * 256 + tid;
    const uint64_t aa0 = bcast2(-2.0f * t2[q0]);
    const uint64_t bb0 = bcast2(-2.0f * t2[NPTS + q0]);
    const uint64_t cc0 = bcast2(-2.0f * t2[2 * NPTS + q0]);
    const uint64_t aa1 = bcast2(-2.0f * t2[q0 + 128]);
    const uint64_t bb1 = bcast2(-2.0f * t2[NPTS + q0 + 128]);
    const uint64_t cc1 = bcast2(-2.0f * t2[2 * NPTS + q0 + 128]);

    // One running min + winning-pair index per query; parity deferred.
    float gm0 = 3.4e38f, gm1 = 3.4e38f;
    int   bi0 = 0,       bi1 = 0;

    const uint32_t sbase = (uint32_t)__cvta_generic_to_shared(refs);

    // v = fma(a,x, fma(b,y, fma(c,z, w))) — identical chain to all passing
    // kernels: every argmin decision bit-identical. Strict '<' on
    // m = min(ve,vo): bi records the FIRST pair attaining the final min.
    #pragma unroll 4
    for (int i = 0; i < CHUNK / 2; ++i) {
        uint64_t x01, y01, z01, w01;
        lds_v2u64(sbase + i * 32,      x01, y01);
        lds_v2u64(sbase + i * 32 + 16, z01, w01);

        uint64_t v0p = fma2(aa0, x01, fma2(bb0, y01, fma2(cc0, z01, w01)));
        uint64_t v1p = fma2(aa1, x01, fma2(bb1, y01, fma2(cc1, z01, w01)));

        float v0e, v0o, v1e, v1o;
        unpack2(v0p, v0e, v0o);
        unpack2(v1p, v1e, v1o);

        float m0 = fminf(v0e, v0o);
        float m1 = fminf(v1e, v1o);
        bool p0 = m0 < gm0;
        bool p1 = m1 < gm1;
        gm0 = fminf(gm0, m0);
        gm1 = fminf(gm1, m1);
        bi0 = p0 ? i : bi0;
        bi1 = p1 ? i : bi1;
    }

    // Epilogue: resolve parity by recomputing the winning pair (bit-exact;
    // gm is a bit-copy of one half). ve == gm -> even (lower index) wins,
    // preserving first-occurrence on intra-pair ties.
    int idx0, idx1;
    {
        uint64_t x01, y01, z01, w01;
        lds_v2u64(sbase + bi0 * 32,      x01, y01);
        lds_v2u64(sbase + bi0 * 32 + 16, z01, w01);
        uint64_t vp = fma2(aa0, x01, fma2(bb0, y01, fma2(cc0, z01, w01)));
        float ve, vo; unpack2(vp, ve, vo);
        idx0 = base + 2 * bi0 + ((ve == gm0) ? 0 : 1);
    }
    {
        uint64_t x01, y01, z01, w01;
        lds_v2u64(sbase + bi1 * 32,      x01, y01);
        lds_v2u64(sbase + bi1 * 32 + 16, z01, w01);
        uint64_t vp = fma2(aa1, x01, fma2(bb1, y01, fma2(cc1, z01, w01)));
        float ve, vo; unpack2(vp, ve, vo);
        idx1 = base + 2 * bi1 + ((ve == gm1) ? 0 : 1);
    }

    g_part[split * NPTS + q0] =
        ((unsigned long long)float_order(gm0) << 32) | (unsigned int)idx0;
    g_part[split * NPTS + q0 + 128] =
        ((unsigned long long)float_order(gm1) << 32) | (unsigned int)idx1;
}

// ===== combine: 8 lanes per query, shfl-reduced. grid(256), block(256). =====
// Lane group g (8 lanes) owns query q; lane j of the group min-combines
// splits {j, j+8, ..., j+56}, then 3 shfl_xor steps reduce the group.
__global__ void __launch_bounds__(256) combine_kernel() {
    const int tid  = threadIdx.x;
    const int q    = (blockIdx.x * 256 + tid) >> 3;   // 8 threads per query
    const int lane = tid & 7;

    unsigned long long m = 0xFFFFFFFFFFFFFFFFull;
    #pragma unroll
    for (int s = 0; s < 8; ++s) {
        unsigned long long v = g_part[(lane + s * 8) * NPTS + q];
        m = (v < m) ? v : m;
    }
    #pragma unroll
    for (int d = 4; d > 0; d >>= 1) {
        unsigned long long o = __shfl_xor_sync(0xFFFFFFFFu, m, d);
        m = (o < m) ? o : m;
    }
    if (lane == 0)
        g_inds[q] = (int)(unsigned int)(m & 0xFFFFFFFFull);
}

// ===== gather: 4 blocks per emb1 row. grid(4*NFEAT=1024), block(256). =====
// Each block loads the full row into smem (L2 dedups the 4x reads) and
// gathers a 2048-query quarter via LDS; float4 coalesced stores.
__global__ void __launch_bounds__(256) gather_kernel(
    const float* __restrict__ emb1,
    float* __restrict__ out)
{
    const int tid     = threadIdx.x;
    const int row     = blockIdx.x >> 2;
    const int quarter = blockIdx.x & 3;

    __shared__ float srow[NPTS];
    const float4* rowsrc = (const float4*)(emb1 + (size_t)row * NPTS);
    float4* srow4 = (float4*)srow;
    #pragma unroll
    for (int i = 0; i < NPTS / 4 / 256; ++i)        // 8 float4 per thread
        srow4[i * 256 + tid] = rowsrc[i * 256 + tid];
    __syncthreads();

    const int joff = quarter * (NPTS / 4);          // 2048-query quarter
    float* dst = out + (size_t)row * NPTS + joff;
    const int* inds = g_inds + joff;
    #pragma unroll
    for (int k = 0; k < 2; ++k) {
        const int j = tid * 4 + k * 1024;
        int4 iv = *(const int4*)(inds + j);
        float4 v = make_float4(srow[iv.x], srow[iv.y], srow[iv.z], srow[iv.w]);
        *(float4*)(dst + j) = v;
    }
}

extern "C" void kernel_launch(void* const* d_in, const int* in_sizes, int n_in,
                              void* d_out, int out_size) {
    const float* emb1 = (const float*)d_in[0];
    const float* emb2 = (const float*)d_in[1];
    const float* t1   = (const float*)d_in[2];
    const float* t2   = (const float*)d_in[3];
    float* out = (float*)d_out;

    nn_argmin_kernel<<<NN_BLOCKS + COPY_BLOCKS, 128>>>(t1, t2, emb2, out);
    combine_kernel<<<256, 256>>>();
    gather_kernel<<<4 * NFEAT, 256>>>(emb1, out);
}

// round 13
// speedup vs baseline: 1.0850x; 1.0106x over previous
#include <cuda_runtime.h>
#include <cstdint>

#define NPTS   8192
#define NFEAT  256
#define SPLITS 32
#define CHUNK  (NPTS / SPLITS)      // 256 refs = 128 pairs -> 4KB smem
#define NN_BLOCKS   (NPTS / 256 * SPLITS)   // 1024 -> single wave incl. copy
#define COPY_BLOCKS 128

// Per-split packed argmin partials: (ordered_d2_bits << 32) | ref_index.
__device__ unsigned long long g_part[SPLITS * NPTS];
__device__ int g_inds[NPTS];

__device__ __forceinline__ unsigned int float_order(float f) {
    unsigned int u = __float_as_uint(f);
    return (u & 0x80000000u) ? ~u : (u | 0x80000000u);
}

// ---- packed f32x2 helpers (FFMA2 is PTX-only; ptxas won't auto-fuse) ----
__device__ __forceinline__ uint64_t bcast2(float f) {
    uint64_t r; asm("mov.b64 %0, {%1, %1};" : "=l"(r) : "f"(f)); return r;
}
__device__ __forceinline__ uint64_t fma2(uint64_t a, uint64_t b, uint64_t c) {
    uint64_t d; asm("fma.rn.f32x2 %0, %1, %2, %3;" : "=l"(d) : "l"(a), "l"(b), "l"(c));
    return d;
}
__device__ __forceinline__ void unpack2(uint64_t v, float& lo, float& hi) {
    asm("mov.b64 {%0, %1}, %2;" : "=f"(lo), "=f"(hi) : "l"(v));
}
__device__ __forceinline__ void lds_v2u64(uint32_t addr, uint64_t& a, uint64_t& b) {
    asm volatile("ld.shared.v2.u64 {%0, %1}, [%2];" : "=l"(a), "=l"(b) : "r"(addr));
}

// grid(NN_BLOCKS + COPY_BLOCKS = 1152), block(128): single wave (~7.8/SM,
// capacity 12). No occupancy cap (caps spill the hot loop — round 9).
// Blocks [0, NN_BLOCKS): argmin. qtile = b & 31, split = b >> 5.
// Blocks [NN_BLOCKS, +COPY_BLOCKS): stream-copy emb2 -> out upper half.
__global__ void __launch_bounds__(128) nn_argmin_kernel(
    const float* __restrict__ t1,   // refs  [3, NPTS]
    const float* __restrict__ t2,   // query [3, NPTS]
    const float* __restrict__ emb2,
    float* __restrict__ out)
{
    const int tid = threadIdx.x;

    if (blockIdx.x >= NN_BLOCKS) {
        const int c = blockIdx.x - NN_BLOCKS;
        const float4* src = (const float4*)emb2;
        float4* dst = (float4*)(out + (size_t)NFEAT * NPTS);
        #pragma unroll
        for (int i = 0; i < 32; ++i) {
            const int o = c * 4096 + i * 128 + tid;
            dst[o] = src[o];
        }
        return;
    }

    __shared__ float4 refs[CHUNK];          // 256 float4 = 4KB
    const int split = blockIdx.x >> 5;
    const int qtile = blockIdx.x & 31;
    const int base  = split * CHUNK;

    // Prologue: each of 128 threads packs one ref pair:
    // pair i -> {x0,x1,y0,y1},{z0,z1,w0,w1}.
    {
        const int r2 = tid * 2;
        float2 x2 = *(const float2*)(t1 + base + r2);
        float2 y2 = *(const float2*)(t1 + NPTS + base + r2);
        float2 z2 = *(const float2*)(t1 + 2 * NPTS + base + r2);
        float w0 = fmaf(x2.x, x2.x, fmaf(y2.x, y2.x, z2.x * z2.x));
        float w1 = fmaf(x2.y, x2.y, fmaf(y2.y, y2.y, z2.y * z2.y));
        refs[2 * tid]     = make_float4(x2.x, x2.y, y2.x, y2.y);
        refs[2 * tid + 1] = make_float4(z2.x, z2.y, w0, w1);
    }
    __syncthreads();

    const int q0 = qtile * 256 + tid;
    const uint64_t aa0 = bcast2(-2.0f * t2[q0]);
    const uint64_t bb0 = bcast2(-2.0f * t2[NPTS + q0]);
    const uint64_t cc0 = bcast2(-2.0f * t2[2 * NPTS + q0]);
    const uint64_t aa1 = bcast2(-2.0f * t2[q0 + 128]);
    const uint64_t bb1 = bcast2(-2.0f * t2[NPTS + q0 + 128]);
    const uint64_t cc1 = bcast2(-2.0f * t2[2 * NPTS + q0 + 128]);

    // One running min + winning-pair index per query; parity deferred.
    float gm0 = 3.4e38f, gm1 = 3.4e38f;
    int   bi0 = 0,       bi1 = 0;

    const uint32_t sbase = (uint32_t)__cvta_generic_to_shared(refs);

    // v = fma(a,x, fma(b,y, fma(c,z, w))) — identical chain to all passing
    // kernels: every argmin decision bit-identical. Strict '<' on
    // m = min(ve,vo): bi records the FIRST pair attaining the final min.
    #pragma unroll 4
    for (int i = 0; i < CHUNK / 2; ++i) {
        uint64_t x01, y01, z01, w01;
        lds_v2u64(sbase + i * 32,      x01, y01);
        lds_v2u64(sbase + i * 32 + 16, z01, w01);

        uint64_t v0p = fma2(aa0, x01, fma2(bb0, y01, fma2(cc0, z01, w01)));
        uint64_t v1p = fma2(aa1, x01, fma2(bb1, y01, fma2(cc1, z01, w01)));

        float v0e, v0o, v1e, v1o;
        unpack2(v0p, v0e, v0o);
        unpack2(v1p, v1e, v1o);

        float m0 = fminf(v0e, v0o);
        float m1 = fminf(v1e, v1o);
        bool p0 = m0 < gm0;
        bool p1 = m1 < gm1;
        gm0 = fminf(gm0, m0);
        gm1 = fminf(gm1, m1);
        bi0 = p0 ? i : bi0;
        bi1 = p1 ? i : bi1;
    }

    // Epilogue: resolve parity by recomputing the winning pair (bit-exact;
    // gm is a bit-copy of one half). ve == gm -> even (lower index) wins,
    // preserving first-occurrence on intra-pair ties.
    int idx0, idx1;
    {
        uint64_t x01, y01, z01, w01;
        lds_v2u64(sbase + bi0 * 32,      x01, y01);
        lds_v2u64(sbase + bi0 * 32 + 16, z01, w01);
        uint64_t vp = fma2(aa0, x01, fma2(bb0, y01, fma2(cc0, z01, w01)));
        float ve, vo; unpack2(vp, ve, vo);
        idx0 = base + 2 * bi0 + ((ve == gm0) ? 0 : 1);
    }
    {
        uint64_t x01, y01, z01, w01;
        lds_v2u64(sbase + bi1 * 32,      x01, y01);
        lds_v2u64(sbase + bi1 * 32 + 16, z01, w01);
        uint64_t vp = fma2(aa1, x01, fma2(bb1, y01, fma2(cc1, z01, w01)));
        float ve, vo; unpack2(vp, ve, vo);
        idx1 = base + 2 * bi1 + ((ve == gm1) ? 0 : 1);
    }

    g_part[split * NPTS + q0] =
        ((unsigned long long)float_order(gm0) << 32) | (unsigned int)idx0;
    g_part[split * NPTS + q0 + 128] =
        ((unsigned long long)float_order(gm1) << 32) | (unsigned int)idx1;
}

// combine: 8 lanes per query, 4 splits per lane, shfl-reduced.
// grid(256), block(256).
__global__ void __launch_bounds__(256) combine_kernel() {
    const int tid  = threadIdx.x;
    const int q    = (blockIdx.x * 256 + tid) >> 3;   // 8 threads per query
    const int lane = tid & 7;

    unsigned long long m = 0xFFFFFFFFFFFFFFFFull;
    #pragma unroll
    for (int s = 0; s < 4; ++s) {
        unsigned long long v = g_part[(lane + s * 8) * NPTS + q];
        m = (v < m) ? v : m;
    }
    #pragma unroll
    for (int d = 4; d > 0; d >>= 1) {
        unsigned long long o = __shfl_xor_sync(0xFFFFFFFFu, m, d);
        m = (o < m) ? o : m;
    }
    if (lane == 0)
        g_inds[q] = (int)(unsigned int)(m & 0xFFFFFFFFull);
}

// gather: 4 blocks per emb1 row. grid(4*NFEAT=1024), block(256).
// Each block loads the full row into smem (L2 dedups the 4x reads) and
// gathers a 2048-query quarter via LDS; float4 coalesced stores.
__global__ void __launch_bounds__(256) gather_kernel(
    const float* __restrict__ emb1,
    float* __restrict__ out)
{
    const int tid     = threadIdx.x;
    const int row     = blockIdx.x >> 2;
    const int quarter = blockIdx.x & 3;

    __shared__ float srow[NPTS];
    const float4* rowsrc = (const float4*)(emb1 + (size_t)row * NPTS);
    float4* srow4 = (float4*)srow;
    #pragma unroll
    for (int i = 0; i < NPTS / 4 / 256; ++i)        // 8 float4 per thread
        srow4[i * 256 + tid] = rowsrc[i * 256 + tid];
    __syncthreads();

    const int joff = quarter * (NPTS / 4);          // 2048-query quarter
    float* dst = out + (size_t)row * NPTS + joff;
    const int* inds = g_inds + joff;
    #pragma unroll
    for (int k = 0; k < 2; ++k) {
        const int j = tid * 4 + k * 1024;
        int4 iv = *(const int4*)(inds + j);
        float4 v = make_float4(srow[iv.x], srow[iv.y], srow[iv.z], srow[iv.w]);
        *(float4*)(dst + j) = v;
    }
}

extern "C" void kernel_launch(void* const* d_in, const int* in_sizes, int n_in,
                              void* d_out, int out_size) {
    const float* emb1 = (const float*)d_in[0];
    const float* emb2 = (const float*)d_in[1];
    const float* t1   = (const float*)d_in[2];
    const float* t2   = (const float*)d_in[3];
    float* out = (float*)d_out;

    nn_argmin_kernel<<<NN_BLOCKS + COPY_BLOCKS, 128>>>(t1, t2, emb2, out);
    combine_kernel<<<256, 256>>>();
    gather_kernel<<<4 * NFEAT, 256>>>(emb1, out);
}